// round 10
// baseline (speedup 1.0000x reference)
#include <cuda_runtime.h>
#include <cuda_bf16.h>
#include <cstdint>

// Single-query attention, B=4096, T=1024, D=64.
//   attn = softmax(mask_fill(q·k^T / 8, pad_mask, -1000))
//   out  = attn @ v
// Outputs: out [B,64] then attn [B,1024] (per out_size).
//
// Masked rows (score -1000 -> exp underflows to exact fp32 0, matching the
// fp32 reference) are never loaded: compacted index list halves K/V traffic.
//
// R10: 64-thread CTAs at 32 CTAs/SM -> 4736 concurrent CTAs >= 4096 grid =
// SINGLE WAVE, no tail quantization (R9 proved tail-filling is worth real
// time: 128-thr CTAs gave 182.7 -> 178.3). sh_idx stored as int16 to fit
// 32 CTAs in the 228KB smem budget (6.9KB/CTA). 32 regs x 2048 thr = full
// RF, enforced by launch_bounds.
//
// Stride-4 group walk keeps the CTA's loads a dense forward-moving window
// (R7: chunked walks regress). __ldcs kept (R8: removing it cost ~6us).
// Phase-1 trip count is WARP-UNIFORM (pair-base loop; R5 deadlock fix).
// outp/qs4 are __align__(16): accessed via float4* (R4 crash fix).

namespace {

constexpr int T_DIM = 1024;
constexpr int D_DIM = 64;
constexpr int NT    = 64;             // threads per CTA
constexpr int NW    = NT / 32;        // 2 warps
constexpr int NG    = NW * 2;         // 4 half-warp groups
constexpr float INV_TEMP = 0.125f;
constexpr float MASK_FILL = -1000.0f;

__global__ __launch_bounds__(NT, 32)
void sdpa_kernel(const float* __restrict__ q,
                 const float* __restrict__ k,
                 const float* __restrict__ v,
                 const int* __restrict__ mask,
                 float* __restrict__ out,
                 float* __restrict__ attn_out)
{
    const int b    = blockIdx.x;
    const int tid  = threadIdx.x;            // 0..63
    const int warp = tid >> 5;               // 0..1
    const int lane = tid & 31;

    __shared__ __align__(16) float4 qs4[D_DIM / 4];   // q row (256 B)
    __shared__ float   sc[T_DIM];            // scores -> probs (4 KB)
    __shared__ short   sh_idx[T_DIM];        // compacted active rows (2 KB)
    __shared__ int     sh_cnt;
    __shared__ float   red_max[NW];
    __shared__ float   red_sum[NW];
    __shared__ __align__(16) float outp[NW][D_DIM];   // per-warp partials (512 B)

    if (tid < D_DIM / 4) {
        qs4[tid] = reinterpret_cast<const float4*>(q + (size_t)b * D_DIM)[tid];
    }
    if (tid == 0) sh_cnt = 0;
    __syncthreads();

    const float4* __restrict__ k4 =
        reinterpret_cast<const float4*>(k + (size_t)b * T_DIM * D_DIM);
    const float4* __restrict__ v4 =
        reinterpret_cast<const float4*>(v + (size_t)b * T_DIM * D_DIM);
    const int* __restrict__ mrow = mask + (size_t)b * T_DIM;

    // ---- phase 0: prefill scores with MASK_FILL + compact unmasked rows ----
    // warp w scans rows [w*512, (w+1)*512); coalesced 4B loads.
    #pragma unroll
    for (int base = warp * 512; base < warp * 512 + 512; base += 32) {
        const int t = base + lane;
        sc[t] = MASK_FILL;
        const bool act = (mrow[t] == 0);
        const unsigned bal = __ballot_sync(0xffffffffu, act);
        int pos;
        if (lane == 0) pos = atomicAdd(&sh_cnt, __popc(bal));
        pos = __shfl_sync(0xffffffffu, pos, 0);
        if (act) {
            sh_idx[pos + __popc(bal & ((1u << lane) - 1u))] = (short)t;
        }
    }
    __syncthreads();

    int nact = sh_cnt;
    const bool all_masked = (nact == 0);             // P ~ 2^-1024; still exact
    if (all_masked) {
        for (int t = tid; t < T_DIM; t += NT) sh_idx[t] = (short)t;
        nact = T_DIM;
    }
    __syncthreads();

    // Warp layout: 16 lanes per row, 2 rows (halves) per warp-iteration.
    const int half = lane >> 4;
    const int qi   = lane & 15;
    const float4 qv = qs4[qi];

    // ---- phase 1: scores for ACTIVE rows only (stride-NG dense window) ----
    if (!all_masked) {
        #pragma unroll 4
        for (int i0 = warp * 2; i0 < nact; i0 += NG) {
            const int  i     = i0 + half;
            const bool valid = (i < nact);
            const int  t     = sh_idx[valid ? i : i0];
            const float4 kv = __ldcs(&k4[t * (D_DIM / 4) + qi]);
            float p = kv.x * qv.x + kv.y * qv.y + kv.z * qv.z + kv.w * qv.w;
            p += __shfl_xor_sync(0xffffffffu, p, 1);
            p += __shfl_xor_sync(0xffffffffu, p, 2);
            p += __shfl_xor_sync(0xffffffffu, p, 4);
            p += __shfl_xor_sync(0xffffffffu, p, 8);
            if (qi == 0 && valid) sc[t] = p * INV_TEMP;
        }
    }
    __syncthreads();

    // ---- phase 2: softmax over all T (masked entries exp-underflow to 0) ----
    float mx = -1e30f;
    #pragma unroll
    for (int t = tid; t < T_DIM; t += NT) mx = fmaxf(mx, sc[t]);
    #pragma unroll
    for (int o = 16; o > 0; o >>= 1)
        mx = fmaxf(mx, __shfl_xor_sync(0xffffffffu, mx, o));
    if (lane == 0) red_max[warp] = mx;
    __syncthreads();

    float bm = red_max[0];
    #pragma unroll
    for (int i = 1; i < NW; i++) bm = fmaxf(bm, red_max[i]);

    float psum = 0.0f;
    #pragma unroll
    for (int t = tid; t < T_DIM; t += NT) {
        const float e = __expf(sc[t] - bm);
        sc[t] = e;
        psum += e;
    }
    #pragma unroll
    for (int o = 16; o > 0; o >>= 1)
        psum += __shfl_xor_sync(0xffffffffu, psum, o);
    if (lane == 0) red_sum[warp] = psum;
    __syncthreads();

    float tot = red_sum[0];
    #pragma unroll
    for (int i = 1; i < NW; i++) tot += red_sum[i];
    const float inv = 1.0f / tot;

    // normalize in shared; emit attn output (coalesced; masked -> exact 0)
    #pragma unroll
    for (int t = tid; t < T_DIM; t += NT) {
        const float pnorm = sc[t] * inv;
        sc[t] = pnorm;
        if (attn_out) attn_out[(size_t)b * T_DIM + t] = pnorm;
    }
    __syncthreads();

    // ---- phase 3: out[d] = sum over ACTIVE rows of p[t] * v[t,d] ----
    // No shuffles inside this loop, so per-half bounds are deadlock-safe.
    const int g = warp * 2 + half;
    float4 acc = make_float4(0.f, 0.f, 0.f, 0.f);
    #pragma unroll 4
    for (int i = g; i < nact; i += NG) {
        const int t = sh_idx[i];
        const float p = sc[t];
        const float4 vv = __ldcs(&v4[t * (D_DIM / 4) + qi]);
        acc.x += p * vv.x;
        acc.y += p * vv.y;
        acc.z += p * vv.z;
        acc.w += p * vv.w;
    }
    acc.x += __shfl_xor_sync(0xffffffffu, acc.x, 16);
    acc.y += __shfl_xor_sync(0xffffffffu, acc.y, 16);
    acc.z += __shfl_xor_sync(0xffffffffu, acc.z, 16);
    acc.w += __shfl_xor_sync(0xffffffffu, acc.w, 16);
    if (half == 0) {
        reinterpret_cast<float4*>(outp[warp])[qi] = acc;
    }
    __syncthreads();

    // NT == D_DIM: every thread writes one output element.
    {
        float s = 0.0f;
        #pragma unroll
        for (int w = 0; w < NW; w++) s += outp[w][tid];
        out[(size_t)b * D_DIM + tid] = s;
    }
}

} // namespace

extern "C" void kernel_launch(void* const* d_in, const int* in_sizes, int n_in,
                              void* d_out, int out_size)
{
    const float* q = (const float*)d_in[0];             // [B,64]
    const float* k = (const float*)d_in[1];             // [B,1024,64]
    const float* v = (const float*)d_in[2];             // [B,1024,64]
    const int*   mask = (const int*)d_in[3];            // [B,1024] bool->4B

    const int B = in_sizes[0] / D_DIM;                  // 4096

    float* out = (float*)d_out;                         // [B,64] first
    float* attn_out = nullptr;
    if (out_size > B * D_DIM) {
        attn_out = out + (size_t)B * D_DIM;             // [B,1024] second
    }

    sdpa_kernel<<<B, NT>>>(q, k, v, mask, out, attn_out);
}

// round 11
// speedup vs baseline: 1.1573x; 1.1573x over previous
#include <cuda_runtime.h>
#include <cuda_bf16.h>
#include <cstdint>

// Single-query attention, B=4096, T=1024, D=64.
//   attn = softmax(mask_fill(q·k^T / 8, pad_mask, -1000))
//   out  = attn @ v
// Outputs: out [B,64] then attn [B,1024] (per out_size).
//
// Masked rows (score -1000 -> exp underflows to exact fp32 0, matching the
// fp32 reference) are never loaded: compacted index list halves K/V traffic.
//
// R11: single-wave launch WITHOUT shrinking CTAs (R10 showed 64-thr CTAs
// lose residency to smem granularity: occ 72.7%, 211us). Keep the proven
// 128-thr / 16-CTA-per-SM shape (R9: 178.3us, occ 85.3%) but halve the
// grid: 2048 CTAs x 2 sequential batch rows each. Concurrent capacity
// (~2020-2368 CTAs) >= 2048 -> one wave, no quantized tail. Smem is reused
// across the two rows, so residency is unchanged.
//
// Stride-8 group walk keeps the CTA's loads a dense forward-moving window
// (R7: chunked walks regress). __ldcs kept (R8: removing it cost ~6us).
// Phase-1 trip count is WARP-UNIFORM (pair-base loop; R5 deadlock fix).
// outp/qs4 are __align__(16): accessed via float4* (R4 crash fix).

namespace {

constexpr int T_DIM = 1024;
constexpr int D_DIM = 64;
constexpr int NT    = 128;            // threads per CTA
constexpr int NW    = NT / 32;        // 4 warps
constexpr int NG    = NW * 2;         // 8 half-warp groups
constexpr int ROWS_PER_CTA = 2;
constexpr float INV_TEMP = 0.125f;
constexpr float MASK_FILL = -1000.0f;

__global__ __launch_bounds__(NT, 16)
void sdpa_kernel(const float* __restrict__ q,
                 const float* __restrict__ k,
                 const float* __restrict__ v,
                 const int* __restrict__ mask,
                 float* __restrict__ out,
                 float* __restrict__ attn_out)
{
    const int tid  = threadIdx.x;            // 0..127
    const int warp = tid >> 5;               // 0..3
    const int lane = tid & 31;

    __shared__ __align__(16) float4 qs4[D_DIM / 4];   // q row (256 B)
    __shared__ float  sc[T_DIM];             // scores -> probs (4 KB)
    __shared__ short  sh_idx[T_DIM];         // compacted active rows (2 KB)
    __shared__ int    sh_cnt;
    __shared__ float  red_max[NW];
    __shared__ float  red_sum[NW];
    __shared__ __align__(16) float outp[NW][D_DIM];   // per-warp partials (1 KB)

    for (int r = 0; r < ROWS_PER_CTA; r++) {
        const int b = blockIdx.x * ROWS_PER_CTA + r;

        if (tid < D_DIM / 4) {
            qs4[tid] =
                reinterpret_cast<const float4*>(q + (size_t)b * D_DIM)[tid];
        }
        if (tid == 0) sh_cnt = 0;
        __syncthreads();

        const float4* __restrict__ k4 =
            reinterpret_cast<const float4*>(k + (size_t)b * T_DIM * D_DIM);
        const float4* __restrict__ v4 =
            reinterpret_cast<const float4*>(v + (size_t)b * T_DIM * D_DIM);
        const int* __restrict__ mrow = mask + (size_t)b * T_DIM;

        // ---- phase 0: prefill MASK_FILL + compact unmasked rows ----
        #pragma unroll
        for (int base = warp * 256; base < warp * 256 + 256; base += 32) {
            const int t = base + lane;
            sc[t] = MASK_FILL;
            const bool act = (mrow[t] == 0);
            const unsigned bal = __ballot_sync(0xffffffffu, act);
            int pos;
            if (lane == 0) pos = atomicAdd(&sh_cnt, __popc(bal));
            pos = __shfl_sync(0xffffffffu, pos, 0);
            if (act) {
                sh_idx[pos + __popc(bal & ((1u << lane) - 1u))] = (short)t;
            }
        }
        __syncthreads();

        int nact = sh_cnt;
        const bool all_masked = (nact == 0);     // P ~ 2^-1024; still exact
        if (all_masked) {
            for (int t = tid; t < T_DIM; t += NT) sh_idx[t] = (short)t;
            nact = T_DIM;
        }
        __syncthreads();

        // Warp layout: 16 lanes per row, 2 rows (halves) per warp-iter.
        const int half = lane >> 4;
        const int qi   = lane & 15;
        const float4 qv = qs4[qi];

        // ---- phase 1: scores for ACTIVE rows (stride-NG dense window) ----
        // Warp-uniform trip count (shuffles inside): pair-base loop; the
        // invalid half loads a safe dummy row and suppresses its store.
        if (!all_masked) {
            #pragma unroll 4
            for (int i0 = warp * 2; i0 < nact; i0 += NG) {
                const int  i     = i0 + half;
                const bool valid = (i < nact);
                const int  t     = sh_idx[valid ? i : i0];
                const float4 kv = __ldcs(&k4[t * (D_DIM / 4) + qi]);
                float p = kv.x * qv.x + kv.y * qv.y + kv.z * qv.z + kv.w * qv.w;
                p += __shfl_xor_sync(0xffffffffu, p, 1);
                p += __shfl_xor_sync(0xffffffffu, p, 2);
                p += __shfl_xor_sync(0xffffffffu, p, 4);
                p += __shfl_xor_sync(0xffffffffu, p, 8);
                if (qi == 0 && valid) sc[t] = p * INV_TEMP;
            }
        }
        __syncthreads();

        // ---- phase 2: softmax over all T (masked -> exp underflow 0) ----
        float mx = -1e30f;
        #pragma unroll
        for (int t = tid; t < T_DIM; t += NT) mx = fmaxf(mx, sc[t]);
        #pragma unroll
        for (int o = 16; o > 0; o >>= 1)
            mx = fmaxf(mx, __shfl_xor_sync(0xffffffffu, mx, o));
        if (lane == 0) red_max[warp] = mx;
        __syncthreads();

        float bm = red_max[0];
        #pragma unroll
        for (int i = 1; i < NW; i++) bm = fmaxf(bm, red_max[i]);

        float psum = 0.0f;
        #pragma unroll
        for (int t = tid; t < T_DIM; t += NT) {
            const float e = __expf(sc[t] - bm);
            sc[t] = e;
            psum += e;
        }
        #pragma unroll
        for (int o = 16; o > 0; o >>= 1)
            psum += __shfl_xor_sync(0xffffffffu, psum, o);
        if (lane == 0) red_sum[warp] = psum;
        __syncthreads();

        float tot = red_sum[0];
        #pragma unroll
        for (int i = 1; i < NW; i++) tot += red_sum[i];
        const float inv = 1.0f / tot;

        // normalize in shared; emit attn output (coalesced)
        #pragma unroll
        for (int t = tid; t < T_DIM; t += NT) {
            const float pnorm = sc[t] * inv;
            sc[t] = pnorm;
            if (attn_out) attn_out[(size_t)b * T_DIM + t] = pnorm;
        }
        __syncthreads();

        // ---- phase 3: out[d] = sum over ACTIVE rows of p[t]*v[t,d] ----
        // No shuffles inside this loop: per-half bounds are deadlock-safe.
        const int g = warp * 2 + half;
        float4 acc = make_float4(0.f, 0.f, 0.f, 0.f);
        #pragma unroll 4
        for (int i = g; i < nact; i += NG) {
            const int t = sh_idx[i];
            const float p = sc[t];
            const float4 vv = __ldcs(&v4[t * (D_DIM / 4) + qi]);
            acc.x += p * vv.x;
            acc.y += p * vv.y;
            acc.z += p * vv.z;
            acc.w += p * vv.w;
        }
        acc.x += __shfl_xor_sync(0xffffffffu, acc.x, 16);
        acc.y += __shfl_xor_sync(0xffffffffu, acc.y, 16);
        acc.z += __shfl_xor_sync(0xffffffffu, acc.z, 16);
        acc.w += __shfl_xor_sync(0xffffffffu, acc.w, 16);
        if (half == 0) {
            reinterpret_cast<float4*>(outp[warp])[qi] = acc;
        }
        __syncthreads();

        if (tid < D_DIM) {
            float s = 0.0f;
            #pragma unroll
            for (int w = 0; w < NW; w++) s += outp[w][tid];
            out[(size_t)b * D_DIM + tid] = s;
        }
        __syncthreads();   // protect smem reuse before next row
    }
}

} // namespace

extern "C" void kernel_launch(void* const* d_in, const int* in_sizes, int n_in,
                              void* d_out, int out_size)
{
    const float* q = (const float*)d_in[0];             // [B,64]
    const float* k = (const float*)d_in[1];             // [B,1024,64]
    const float* v = (const float*)d_in[2];             // [B,1024,64]
    const int*   mask = (const int*)d_in[3];            // [B,1024] bool->4B

    const int B = in_sizes[0] / D_DIM;                  // 4096

    float* out = (float*)d_out;                         // [B,64] first
    float* attn_out = nullptr;
    if (out_size > B * D_DIM) {
        attn_out = out + (size_t)B * D_DIM;             // [B,1024] second
    }

    sdpa_kernel<<<B / ROWS_PER_CTA, NT>>>(q, k, v, mask, out, attn_out);
}

// round 16
// speedup vs baseline: 1.1612x; 1.0033x over previous
#include <cuda_runtime.h>
#include <cuda_bf16.h>
#include <cstdint>

// Single-query attention, B=4096, T=1024, D=64.
//   attn = softmax(mask_fill(q·k^T / 8, pad_mask, -1000))
//   out  = attn @ v
// Outputs: out [B,64] then attn [B,1024] (per out_size).
//
// Masked rows (score -1000 -> exp underflows to exact fp32 0, matching the
// fp32 reference) are never loaded: compacted index list halves K/V traffic.
//
// Config = R9 (best: 178.3us, DRAM 77.1%, occ 85.3%): 128-thr CTAs,
// grid 4096, 16 CTAs/SM target. R10 (64-thr CTAs) and R11 (2 rows/CTA)
// both proved worse — R9's 1.73-wave stagger + full residency is the
// concurrency optimum for this chip.
//
// R12 delta: pure cache-policy hints, zero register impact —
//   * __stcs on attn/out stores (streaming writes, evict-first in L2; keep
//     the 17MB write stream from displacing in-flight K/V read sectors)
//   * __ldcs on the mask scan (16MB, zero reuse), matching K/V policy.
//
// Stride-8 group walk keeps the CTA's loads a dense forward-moving window
// (R7: chunked walks regress). __ldcs on K/V kept (R8: removing cost 6us).
// Phase-1 trip count is WARP-UNIFORM (pair-base loop; R5 deadlock fix).
// outp/qs4 are __align__(16): accessed via float4* (R4 crash fix).

namespace {

constexpr int T_DIM = 1024;
constexpr int D_DIM = 64;
constexpr int NT    = 128;            // threads per CTA
constexpr int NW    = NT / 32;        // 4 warps
constexpr int NG    = NW * 2;         // 8 half-warp groups
constexpr float INV_TEMP = 0.125f;
constexpr float MASK_FILL = -1000.0f;

__global__ __launch_bounds__(NT, 16)
void sdpa_kernel(const float* __restrict__ q,
                 const float* __restrict__ k,
                 const float* __restrict__ v,
                 const int* __restrict__ mask,
                 float* __restrict__ out,
                 float* __restrict__ attn_out)
{
    const int b    = blockIdx.x;
    const int tid  = threadIdx.x;            // 0..127
    const int warp = tid >> 5;               // 0..3
    const int lane = tid & 31;

    __shared__ __align__(16) float4 qs4[D_DIM / 4];   // q row (256 B)
    __shared__ float  sc[T_DIM];             // scores -> probs (4 KB)
    __shared__ short  sh_idx[T_DIM];         // compacted active rows (2 KB)
    __shared__ int    sh_cnt;
    __shared__ float  red_max[NW];
    __shared__ float  red_sum[NW];
    __shared__ __align__(16) float outp[NW][D_DIM];   // per-warp partials (1 KB)

    if (tid < D_DIM / 4) {
        qs4[tid] = reinterpret_cast<const float4*>(q + (size_t)b * D_DIM)[tid];
    }
    if (tid == 0) sh_cnt = 0;
    __syncthreads();

    const float4* __restrict__ k4 =
        reinterpret_cast<const float4*>(k + (size_t)b * T_DIM * D_DIM);
    const float4* __restrict__ v4 =
        reinterpret_cast<const float4*>(v + (size_t)b * T_DIM * D_DIM);
    const int* __restrict__ mrow = mask + (size_t)b * T_DIM;

    // ---- phase 0: prefill scores with MASK_FILL + compact unmasked rows ----
    // warp w scans rows [w*256, (w+1)*256); coalesced 4B streaming loads.
    #pragma unroll
    for (int base = warp * 256; base < warp * 256 + 256; base += 32) {
        const int t = base + lane;
        sc[t] = MASK_FILL;
        const bool act = (__ldcs(&mrow[t]) == 0);
        const unsigned bal = __ballot_sync(0xffffffffu, act);
        int pos;
        if (lane == 0) pos = atomicAdd(&sh_cnt, __popc(bal));
        pos = __shfl_sync(0xffffffffu, pos, 0);
        if (act) {
            sh_idx[pos + __popc(bal & ((1u << lane) - 1u))] = (short)t;
        }
    }
    __syncthreads();

    int nact = sh_cnt;
    const bool all_masked = (nact == 0);             // P ~ 2^-1024; still exact
    if (all_masked) {
        for (int t = tid; t < T_DIM; t += NT) sh_idx[t] = (short)t;
        nact = T_DIM;
    }
    __syncthreads();

    // Warp layout: 16 lanes per row, 2 rows (halves) per warp-iteration.
    const int half = lane >> 4;
    const int qi   = lane & 15;
    const float4 qv = qs4[qi];

    // ---- phase 1: scores for ACTIVE rows only (stride-NG dense window) ----
    // Warp-uniform trip count (shuffles inside): pair-base loop; the invalid
    // half loads a safe dummy row and suppresses its store.
    if (!all_masked) {
        #pragma unroll 4
        for (int i0 = warp * 2; i0 < nact; i0 += NG) {
            const int  i     = i0 + half;
            const bool valid = (i < nact);
            const int  t     = sh_idx[valid ? i : i0];
            const float4 kv = __ldcs(&k4[t * (D_DIM / 4) + qi]);
            float p = kv.x * qv.x + kv.y * qv.y + kv.z * qv.z + kv.w * qv.w;
            p += __shfl_xor_sync(0xffffffffu, p, 1);
            p += __shfl_xor_sync(0xffffffffu, p, 2);
            p += __shfl_xor_sync(0xffffffffu, p, 4);
            p += __shfl_xor_sync(0xffffffffu, p, 8);
            if (qi == 0 && valid) sc[t] = p * INV_TEMP;
        }
    }
    __syncthreads();

    // ---- phase 2: softmax over all T (masked entries exp-underflow to 0) ----
    float mx = -1e30f;
    #pragma unroll
    for (int t = tid; t < T_DIM; t += NT) mx = fmaxf(mx, sc[t]);
    #pragma unroll
    for (int o = 16; o > 0; o >>= 1)
        mx = fmaxf(mx, __shfl_xor_sync(0xffffffffu, mx, o));
    if (lane == 0) red_max[warp] = mx;
    __syncthreads();

    float bm = red_max[0];
    #pragma unroll
    for (int i = 1; i < NW; i++) bm = fmaxf(bm, red_max[i]);

    float psum = 0.0f;
    #pragma unroll
    for (int t = tid; t < T_DIM; t += NT) {
        const float e = __expf(sc[t] - bm);
        sc[t] = e;
        psum += e;
    }
    #pragma unroll
    for (int o = 16; o > 0; o >>= 1)
        psum += __shfl_xor_sync(0xffffffffu, psum, o);
    if (lane == 0) red_sum[warp] = psum;
    __syncthreads();

    float tot = red_sum[0];
    #pragma unroll
    for (int i = 1; i < NW; i++) tot += red_sum[i];
    const float inv = 1.0f / tot;

    // normalize in shared; emit attn output (coalesced streaming stores)
    #pragma unroll
    for (int t = tid; t < T_DIM; t += NT) {
        const float pnorm = sc[t] * inv;
        sc[t] = pnorm;
        if (attn_out) __stcs(&attn_out[(size_t)b * T_DIM + t], pnorm);
    }
    __syncthreads();

    // ---- phase 3: out[d] = sum over ACTIVE rows of p[t] * v[t,d] ----
    // No shuffles inside this loop, so per-half bounds are deadlock-safe.
    const int g = warp * 2 + half;
    float4 acc = make_float4(0.f, 0.f, 0.f, 0.f);
    #pragma unroll 4
    for (int i = g; i < nact; i += NG) {
        const int t = sh_idx[i];
        const float p = sc[t];
        const float4 vv = __ldcs(&v4[t * (D_DIM / 4) + qi]);
        acc.x += p * vv.x;
        acc.y += p * vv.y;
        acc.z += p * vv.z;
        acc.w += p * vv.w;
    }
    acc.x += __shfl_xor_sync(0xffffffffu, acc.x, 16);
    acc.y += __shfl_xor_sync(0xffffffffu, acc.y, 16);
    acc.z += __shfl_xor_sync(0xffffffffu, acc.z, 16);
    acc.w += __shfl_xor_sync(0xffffffffu, acc.w, 16);
    if (half == 0) {
        reinterpret_cast<float4*>(outp[warp])[qi] = acc;
    }
    __syncthreads();

    if (tid < D_DIM) {
        float s = 0.0f;
        #pragma unroll
        for (int w = 0; w < NW; w++) s += outp[w][tid];
        __stcs(&out[(size_t)b * D_DIM + tid], s);
    }
}

} // namespace

extern "C" void kernel_launch(void* const* d_in, const int* in_sizes, int n_in,
                              void* d_out, int out_size)
{
    const float* q = (const float*)d_in[0];             // [B,64]
    const float* k = (const float*)d_in[1];             // [B,1024,64]
    const float* v = (const float*)d_in[2];             // [B,1024,64]
    const int*   mask = (const int*)d_in[3];            // [B,1024] bool->4B

    const int B = in_sizes[0] / D_DIM;                  // 4096

    float* out = (float*)d_out;                         // [B,64] first
    float* attn_out = nullptr;
    if (out_size > B * D_DIM) {
        attn_out = out + (size_t)B * D_DIM;             // [B,1024] second
    }

    sdpa_kernel<<<B, NT>>>(q, k, v, mask, out, attn_out);
}

// round 17
// speedup vs baseline: 1.2025x; 1.0356x over previous
#include <cuda_runtime.h>
#include <cuda_bf16.h>
#include <cstdint>

// Single-query attention, B=4096, T=1024, D=64.
//   attn = softmax(mask_fill(q·k^T / 8, pad_mask, -1000))
//   out  = attn @ v
// Outputs: out [B,64] then attn [B,1024] (per out_size).
//
// Masked rows (score -1000 -> exp underflows to exact fp32 0, matching the
// fp32 reference) are never loaded: compacted index list halves K/V traffic.
//
// Config = R9 (best: 178.3us, DRAM 77.1%, occ 85.3%): 128-thr CTAs,
// grid 4096, 16 CTAs/SM, 32 regs. Proven against: chunked walks (R7),
// no-ldcs (R8), 64-thr CTAs (R10), 2 rows/CTA (R11), store hints (R12).
//
// R17 delta: vectorize the scalar phases (instruction count only):
//   * phase 0: int4 mask loads (4 rows per 16B load), 4 ballot rounds per
//     128 rows, float4 MASK_FILL prefill
//   * phase 2: float4 passes over sc[] for max/exp/normalize, float4 attn
//     stores (STG.128 instead of 4x STG.32)
//
// Phase-1 trip count is WARP-UNIFORM (pair-base loop; R5 deadlock fix).
// sc/outp/qs4 are __align__(16): accessed via float4* (R4 crash fix).

namespace {

constexpr int T_DIM = 1024;
constexpr int D_DIM = 64;
constexpr int NT    = 128;            // threads per CTA
constexpr int NW    = NT / 32;        // 4 warps
constexpr int NG    = NW * 2;         // 8 half-warp groups
constexpr float INV_TEMP = 0.125f;
constexpr float MASK_FILL = -1000.0f;

__global__ __launch_bounds__(NT, 16)
void sdpa_kernel(const float* __restrict__ q,
                 const float* __restrict__ k,
                 const float* __restrict__ v,
                 const int* __restrict__ mask,
                 float* __restrict__ out,
                 float* __restrict__ attn_out)
{
    const int b    = blockIdx.x;
    const int tid  = threadIdx.x;            // 0..127
    const int warp = tid >> 5;               // 0..3
    const int lane = tid & 31;

    __shared__ __align__(16) float4 qs4[D_DIM / 4];   // q row (256 B)
    __shared__ __align__(16) float  sc[T_DIM];        // scores -> probs (4 KB)
    __shared__ short  sh_idx[T_DIM];         // compacted active rows (2 KB)
    __shared__ int    sh_cnt;
    __shared__ float  red_max[NW];
    __shared__ float  red_sum[NW];
    __shared__ __align__(16) float outp[NW][D_DIM];   // per-warp partials (1 KB)

    if (tid < D_DIM / 4) {
        qs4[tid] = reinterpret_cast<const float4*>(q + (size_t)b * D_DIM)[tid];
    }
    if (tid == 0) sh_cnt = 0;
    __syncthreads();

    const float4* __restrict__ k4 =
        reinterpret_cast<const float4*>(k + (size_t)b * T_DIM * D_DIM);
    const float4* __restrict__ v4 =
        reinterpret_cast<const float4*>(v + (size_t)b * T_DIM * D_DIM);
    const int4* __restrict__ mrow4 =
        reinterpret_cast<const int4*>(mask + (size_t)b * T_DIM);
    float4* sc4 = reinterpret_cast<float4*>(sc);

    // ---- phase 0: prefill MASK_FILL + compact unmasked rows (vectorized) --
    // warp w covers rows [w*256, (w+1)*256): 2 iters of 128 rows (int4/lane).
    #pragma unroll
    for (int it = 0; it < 2; it++) {
        const int base = warp * 256 + it * 128;      // first row this iter
        const int t0   = base + lane * 4;            // this lane's 4 rows
        const int4 mv  = mrow4[t0 >> 2];
        sc4[t0 >> 2] = make_float4(MASK_FILL, MASK_FILL, MASK_FILL, MASK_FILL);

        const bool a0 = (mv.x == 0), a1 = (mv.y == 0),
                   a2 = (mv.z == 0), a3 = (mv.w == 0);
        const unsigned b0 = __ballot_sync(0xffffffffu, a0);
        const unsigned b1 = __ballot_sync(0xffffffffu, a1);
        const unsigned b2 = __ballot_sync(0xffffffffu, a2);
        const unsigned b3 = __ballot_sync(0xffffffffu, a3);
        const int tot = __popc(b0) + __popc(b1) + __popc(b2) + __popc(b3);

        int pos;
        if (lane == 0) pos = atomicAdd(&sh_cnt, tot);
        pos = __shfl_sync(0xffffffffu, pos, 0);

        const unsigned lm = (1u << lane) - 1u;
        const int o1 = pos + __popc(b0);
        const int o2 = o1 + __popc(b1);
        const int o3 = o2 + __popc(b2);
        if (a0) sh_idx[pos + __popc(b0 & lm)] = (short)(t0 + 0);
        if (a1) sh_idx[o1  + __popc(b1 & lm)] = (short)(t0 + 1);
        if (a2) sh_idx[o2  + __popc(b2 & lm)] = (short)(t0 + 2);
        if (a3) sh_idx[o3  + __popc(b3 & lm)] = (short)(t0 + 3);
    }
    __syncthreads();

    int nact = sh_cnt;
    const bool all_masked = (nact == 0);             // P ~ 2^-1024; still exact
    if (all_masked) {
        for (int t = tid; t < T_DIM; t += NT) sh_idx[t] = (short)t;
        nact = T_DIM;
    }
    __syncthreads();

    // Warp layout: 16 lanes per row, 2 rows (halves) per warp-iteration.
    const int half = lane >> 4;
    const int qi   = lane & 15;
    const float4 qv = qs4[qi];

    // ---- phase 1: scores for ACTIVE rows only (stride-NG dense window) ----
    // Warp-uniform trip count (shuffles inside): pair-base loop; the invalid
    // half loads a safe dummy row and suppresses its store.
    if (!all_masked) {
        #pragma unroll 4
        for (int i0 = warp * 2; i0 < nact; i0 += NG) {
            const int  i     = i0 + half;
            const bool valid = (i < nact);
            const int  t     = sh_idx[valid ? i : i0];
            const float4 kv = __ldcs(&k4[t * (D_DIM / 4) + qi]);
            float p = kv.x * qv.x + kv.y * qv.y + kv.z * qv.z + kv.w * qv.w;
            p += __shfl_xor_sync(0xffffffffu, p, 1);
            p += __shfl_xor_sync(0xffffffffu, p, 2);
            p += __shfl_xor_sync(0xffffffffu, p, 4);
            p += __shfl_xor_sync(0xffffffffu, p, 8);
            if (qi == 0 && valid) sc[t] = p * INV_TEMP;
        }
    }
    __syncthreads();

    // ---- phase 2: softmax over all T, float4 passes ----
    float mx = -1e30f;
    #pragma unroll
    for (int i = tid; i < T_DIM / 4; i += NT) {
        const float4 s4 = sc4[i];
        mx = fmaxf(mx, fmaxf(fmaxf(s4.x, s4.y), fmaxf(s4.z, s4.w)));
    }
    #pragma unroll
    for (int o = 16; o > 0; o >>= 1)
        mx = fmaxf(mx, __shfl_xor_sync(0xffffffffu, mx, o));
    if (lane == 0) red_max[warp] = mx;
    __syncthreads();

    float bm = red_max[0];
    #pragma unroll
    for (int i = 1; i < NW; i++) bm = fmaxf(bm, red_max[i]);

    float psum = 0.0f;
    #pragma unroll
    for (int i = tid; i < T_DIM / 4; i += NT) {
        float4 s4 = sc4[i];
        s4.x = __expf(s4.x - bm);
        s4.y = __expf(s4.y - bm);
        s4.z = __expf(s4.z - bm);
        s4.w = __expf(s4.w - bm);
        sc4[i] = s4;
        psum += (s4.x + s4.y) + (s4.z + s4.w);
    }
    #pragma unroll
    for (int o = 16; o > 0; o >>= 1)
        psum += __shfl_xor_sync(0xffffffffu, psum, o);
    if (lane == 0) red_sum[warp] = psum;
    __syncthreads();

    float tot = red_sum[0];
    #pragma unroll
    for (int i = 1; i < NW; i++) tot += red_sum[i];
    const float inv = 1.0f / tot;

    // normalize in shared; emit attn output (float4 STG.128, coalesced)
    {
        float4* __restrict__ ao4 = attn_out
            ? reinterpret_cast<float4*>(attn_out + (size_t)b * T_DIM)
            : nullptr;
        #pragma unroll
        for (int i = tid; i < T_DIM / 4; i += NT) {
            float4 p4 = sc4[i];
            p4.x *= inv; p4.y *= inv; p4.z *= inv; p4.w *= inv;
            sc4[i] = p4;
            if (ao4) ao4[i] = p4;
        }
    }
    __syncthreads();

    // ---- phase 3: out[d] = sum over ACTIVE rows of p[t] * v[t,d] ----
    // No shuffles inside this loop, so per-half bounds are deadlock-safe.
    const int g = warp * 2 + half;
    float4 acc = make_float4(0.f, 0.f, 0.f, 0.f);
    #pragma unroll 4
    for (int i = g; i < nact; i += NG) {
        const int t = sh_idx[i];
        const float p = sc[t];
        const float4 vv = __ldcs(&v4[t * (D_DIM / 4) + qi]);
        acc.x += p * vv.x;
        acc.y += p * vv.y;
        acc.z += p * vv.z;
        acc.w += p * vv.w;
    }
    acc.x += __shfl_xor_sync(0xffffffffu, acc.x, 16);
    acc.y += __shfl_xor_sync(0xffffffffu, acc.y, 16);
    acc.z += __shfl_xor_sync(0xffffffffu, acc.z, 16);
    acc.w += __shfl_xor_sync(0xffffffffu, acc.w, 16);
    if (half == 0) {
        reinterpret_cast<float4*>(outp[warp])[qi] = acc;
    }
    __syncthreads();

    if (tid < D_DIM) {
        float s = 0.0f;
        #pragma unroll
        for (int w = 0; w < NW; w++) s += outp[w][tid];
        out[(size_t)b * D_DIM + tid] = s;
    }
}

} // namespace

extern "C" void kernel_launch(void* const* d_in, const int* in_sizes, int n_in,
                              void* d_out, int out_size)
{
    const float* q = (const float*)d_in[0];             // [B,64]
    const float* k = (const float*)d_in[1];             // [B,1024,64]
    const float* v = (const float*)d_in[2];             // [B,1024,64]
    const int*   mask = (const int*)d_in[3];            // [B,1024] bool->4B

    const int B = in_sizes[0] / D_DIM;                  // 4096

    float* out = (float*)d_out;                         // [B,64] first
    float* attn_out = nullptr;
    if (out_size > B * D_DIM) {
        attn_out = out + (size_t)B * D_DIM;             // [B,1024] second
    }

    sdpa_kernel<<<B, NT>>>(q, k, v, mask, out, attn_out);
}